// round 7
// baseline (speedup 1.0000x reference)
#include <cuda_runtime.h>
#include <cuda_bf16.h>
#include <math.h>
#include <stdint.h>

// ---------------------------------------------------------------------------
// ConvLSTM (2 layers, 12 steps) — tensor-core implicit GEMM, bf16 2-term split.
// Activations stored as channel-pair planes: uint32 = {bf16 ch2p | bf16 ch2p+1}.
// cin reordered: [h pairs][extra pairs]; weights repacked to match.
// R6: warp tile 8px x 8 rows (nt=8), 256-thread blocks -> 2x A-fragment reuse,
//     smem wavefronts drop below HMMA issue -> tensor-bound.
// ---------------------------------------------------------------------------

#define TSTEPS 12
#define NCHUNK 9

__device__ uint32_t g_h0p[2u * 16u * 64u * 2u * 4096u];  // h0 pair planes (hi,lo)
__device__ uint32_t g_h1p[2u * 16u * 6u  * 2u * 4096u];  // h1 pair planes
__device__ uint32_t g_xp [12u * 16u * 2u * 4096u];       // x pair planes per t
__device__ float    g_c0 [16u * 128u * 4096u];
__device__ float    g_c1 [16u * 12u  * 4096u];
__device__ float    g_h1f[16u * 12u * 4096u];            // float h1 (output)
__device__ uint32_t g_wp0[8u * 9u * 9216u];              // frag-packed weights
__device__ uint32_t g_wp1[1u * 9u * 9216u];

#define SW_ACT_S   5824u            // one split: 8 planes * 728 words
#define SW_ACT_BUF 11648u           // hi + lo
#define SW_W_OFF   23296u
#define SW_W_BUF   9216u
#define SMEM_BYTES ((23296u + 18432u) * 4u)   // 166,912 B

// -------------------- helpers ----------------------------------------------
__device__ __forceinline__ void mma_bf16(float* d, const uint32_t* a,
                                         uint32_t b0, uint32_t b1) {
    asm volatile(
        "mma.sync.aligned.m16n8k16.row.col.f32.bf16.bf16.f32 "
        "{%0,%1,%2,%3}, {%4,%5,%6,%7}, {%8,%9}, {%0,%1,%2,%3};"
        : "+f"(d[0]), "+f"(d[1]), "+f"(d[2]), "+f"(d[3])
        : "r"(a[0]), "r"(a[1]), "r"(a[2]), "r"(a[3]), "r"(b0), "r"(b1));
}
__device__ __forceinline__ uint32_t smaddr(const void* p) {
    return (uint32_t)__cvta_generic_to_shared(p);
}
__device__ __forceinline__ void cpa16(uint32_t dst, const void* src) {
    asm volatile("cp.async.cg.shared.global [%0], [%1], 16;" :: "r"(dst), "l"(src));
}
__device__ __forceinline__ uint32_t pack_bf(float a, float b) {
    return (uint32_t)__bfloat16_as_ushort(__float2bfloat16_rn(a)) |
           ((uint32_t)__bfloat16_as_ushort(__float2bfloat16_rn(b)) << 16);
}
__device__ __forceinline__ float bflo(float v) {
    return v - __bfloat162float(__float2bfloat16_rn(v));
}
__device__ __forceinline__ float sigf(float x) { return 1.f / (1.f + __expf(-x)); }

// -------------------- init kernels -----------------------------------------
__global__ void zero_init_kernel() {
    size_t tid = (size_t)blockIdx.x * blockDim.x + threadIdx.x;
    size_t st  = (size_t)gridDim.x * blockDim.x;
    const size_t nh0 = (size_t)2 * 16 * 64 * 2 * 4096;
    const size_t nh1 = (size_t)2 * 16 * 6 * 2 * 4096;
    const size_t nc0 = (size_t)16 * 128 * 4096;
    const size_t nc1 = (size_t)16 * 12 * 4096;
    for (size_t i = tid; i < nh0; i += st) g_h0p[i] = 0u;
    for (size_t i = tid; i < nh1; i += st) g_h1p[i] = 0u;
    for (size_t i = tid; i < nc0; i += st) g_c0[i] = 0.f;
    for (size_t i = tid; i < nc1; i += st) g_c1[i] = 0.f;
}

__global__ void xprep_kernel(const float* __restrict__ hist) {
    int n = TSTEPS * 16 * 4096;
    for (int i = blockIdx.x * blockDim.x + threadIdx.x; i < n;
         i += gridDim.x * blockDim.x) {
        int px = i & 4095, b = (i >> 12) & 15, t = i >> 16;
        float v = hist[((size_t)b * TSTEPS + t) * 4096 + px];
        float hi = __bfloat162float(__float2bfloat16_rn(v));
        g_xp[(((size_t)t * 16 + b) * 2 + 0) * 4096 + px] = pack_bf(v, 0.f);
        g_xp[(((size_t)t * 16 + b) * 2 + 1) * 4096 + px] = pack_bf(v - hi, 0.f);
    }
}

// Weights -> A-fragment order: [hb][chunk][ ((tap*4+g)*2+s)*128 + lane*4 + r ]
// reg r: m = lane/4 + (r&1)*8 ; pair = lane%4 + ((r>>1)&1)*4
__global__ void repack_w(const float* __restrict__ W, uint32_t* __restrict__ Wp,
                         int HID, int CIN, int NHB, int layer) {
    int total = NHB * NCHUNK * 9216;
    for (int idx = blockIdx.x * blockDim.x + threadIdx.x; idx < total;
         idx += gridDim.x * blockDim.x) {
        int wrd = idx % 9216, rest = idx / 9216;
        int c = rest % NCHUNK, hb = rest / NCHUNK;
        int r = wrd & 3, lane = (wrd >> 2) & 31, sgt = wrd >> 7;
        int s = sgt & 1, g = (sgt >> 1) & 3, t = sgt >> 3;
        int m  = (lane >> 2) + (r & 1) * 8;
        int pr = (lane & 3) + ((r >> 1) & 1) * 4;
        int p  = c * 8 + pr;
        int hid = hb * 16 + m;
        int k0 = -1, k1 = -1;
        if (layer == 0) {
            if (p < 64)       { k0 = 2 * p + 1; k1 = 2 * p + 2; }
            else if (p == 64) { k0 = 0; }
        } else {
            if (p < 64)      { k0 = 2 * p; k1 = 2 * p + 1; }
            else if (p < 70) { k0 = 128 + 2 * (p - 64); k1 = k0 + 1; }
        }
        float w0 = 0.f, w1 = 0.f;
        if (hid < HID) {
            if (k0 >= 0) w0 = W[((size_t)(g * HID + hid) * CIN + k0) * 9 + t];
            if (k1 >= 0) w1 = W[((size_t)(g * HID + hid) * CIN + k1) * 9 + t];
        }
        Wp[idx] = (s == 0) ? pack_bf(w0, w1) : pack_bf(bflo(w0), bflo(w1));
    }
}

// -------------------- fused conv + LSTM step --------------------------------
// Grid (8 y-tiles, NHB, 16 batch), block 256 = 8 warps (wx 0..7).
// Warp: 16 hid x 4 gates x 64 px (8-px strip, 8 rows). 128 f32 accs/thread.
template <int NPA, int NPB, int HID>
__global__ __launch_bounds__(256, 1)
void conv_step(const uint32_t* __restrict__ actA,   // [b][NPA][2][4096]
               const uint32_t* __restrict__ actB,   // [b][NPB][2][4096]
               const uint32_t* __restrict__ Wg,     // [hb][9][9216]
               const float*    __restrict__ bias,
               float*          __restrict__ cbuf,   // [b][HID][4096]
               uint32_t*       __restrict__ hout,   // [b][HID/2][2][4096]
               float*          __restrict__ hfout) {
    extern __shared__ uint32_t sm[];
    const int tid = threadIdx.x;
    const int lane = tid & 31, warp = tid >> 5;
    const int tg = lane & 3, gq = lane >> 2;
    const int wx = warp;                 // 0..7 (8-px strip)
    const int y0 = blockIdx.x * 8;
    const int hb = blockIdx.y;
    const int b  = blockIdx.z;
    const uint32_t* wgm = Wg + (size_t)hb * NCHUNK * 9216;

    // zero halo columns (0..3, 68..71) for all planes, both buffers
    for (int u = tid; u < 640; u += 256) {
        int side = u & 1, v = u >> 1;
        int r = v % 10, p = (v / 10) & 7, s = (v / 80) & 1, bfi = v / 160;
        uint32_t* dst = sm + bfi * SW_ACT_BUF + s * SW_ACT_S + p * 728 +
                        r * 72 + (side ? 68 : 0);
        *(uint4*)dst = make_uint4(0, 0, 0, 0);
    }

    float acc[4][8][4];
#pragma unroll
    for (int g = 0; g < 4; g++)
#pragma unroll
        for (int n = 0; n < 8; n++)
#pragma unroll
            for (int r = 0; r < 4; r++) acc[g][n][r] = 0.f;

    auto ldchunk = [&](int c, int bfi) {
#pragma unroll
        for (int k = 0; k < 10; k++) {
            int u = tid + k * 256;               // 2560 uint4: act data
            {
                int p = u & 7, s = (u >> 3) & 1, rest = u >> 4;
                int r = rest % 10, seg = rest / 10;     // seg: 16 x 4px
                int pair = c * 8 + p;
                int y = y0 + r - 1;
                uint32_t* dst = sm + bfi * SW_ACT_BUF + s * SW_ACT_S +
                                p * 728 + r * 72 + 4 + seg * 4;
                const uint32_t* src = nullptr;
                if ((unsigned)y < 64u) {
                    if (pair < NPA)
                        src = actA + (((size_t)b * NPA + pair) * 2 + s) * 4096 +
                              y * 64 + seg * 4;
                    else if (pair < NPA + NPB)
                        src = actB + (((size_t)b * NPB + (pair - NPA)) * 2 + s) * 4096 +
                              y * 64 + seg * 4;
                }
                if (src) cpa16(smaddr(dst), src);
                else     *(uint4*)dst = make_uint4(0, 0, 0, 0);
            }
        }
        const uint32_t* wsrc = wgm + (size_t)c * 9216;
        uint32_t* wdst = sm + SW_W_OFF + bfi * SW_W_BUF;
#pragma unroll
        for (int k = 0; k < 9; k++) {
            int u = tid + k * 256;               // 2304 uint4: weights
            cpa16(smaddr(wdst + u * 4), wsrc + u * 4);
        }
        asm volatile("cp.async.commit_group;");
    };

    ldchunk(0, 0);

    for (int c = 0; c < NCHUNK; c++) {
        const int bfi = c & 1;
        if (c + 1 < NCHUNK) {
            ldchunk(c + 1, bfi ^ 1);
            asm volatile("cp.async.wait_group 1;");
        } else {
            asm volatile("cp.async.wait_group 0;");
        }
        __syncthreads();

        const uint32_t* ws = sm + SW_W_OFF + bfi * SW_W_BUF;
        const uint32_t* aH = sm + bfi * SW_ACT_BUF;
        const uint32_t* aL = aH + SW_ACT_S;

#pragma unroll
        for (int ky = 0; ky < 3; ky++) {
#pragma unroll
            for (int kx = 0; kx < 3; kx++) {
                const int t = ky * 3 + kx;
                const int cb = 4 + wx * 8 + gq + kx - 1;
                uint32_t bh[8][2], bl[8][2];
#pragma unroll
                for (int nt = 0; nt < 8; nt++) {
                    int o0 = tg * 728 + (ky + nt) * 72 + cb;
                    bh[nt][0] = aH[o0]; bh[nt][1] = aH[o0 + 4 * 728];
                    bl[nt][0] = aL[o0]; bl[nt][1] = aL[o0 + 4 * 728];
                }
#pragma unroll
                for (int g = 0; g < 4; g++) {
                    uint4 ah = *(const uint4*)(ws + ((t * 4 + g) * 2 + 0) * 128 + lane * 4);
                    uint4 al = *(const uint4*)(ws + ((t * 4 + g) * 2 + 1) * 128 + lane * 4);
#pragma unroll
                    for (int nt = 0; nt < 8; nt++) {
                        mma_bf16(acc[g][nt], (const uint32_t*)&ah, bh[nt][0], bh[nt][1]);
                        mma_bf16(acc[g][nt], (const uint32_t*)&ah, bl[nt][0], bl[nt][1]);
                        mma_bf16(acc[g][nt], (const uint32_t*)&al, bh[nt][0], bh[nt][1]);
                    }
                }
            }
        }
        __syncthreads();
    }

    // ---- LSTM epilogue -----------------------------------------------------
    const int xpx = wx * 8 + tg * 2;
#pragma unroll
    for (int part = 0; part < 2; part++) {
        const int hid = hb * 16 + gq + part * 8;
        const bool hv = (hid < HID);
        float bi = 0.f, bfv = 0.f, bo = 0.f, bg = 0.f;
        if (hv) {
            bi = bias[hid]; bfv = bias[HID + hid];
            bo = bias[2 * HID + hid]; bg = bias[3 * HID + hid];
        }
#pragma unroll
        for (int nt = 0; nt < 8; nt++) {
            const int y = y0 + nt;
            const size_t coff =
                ((size_t)(b * HID + (hv ? hid : 0))) * 4096 + (size_t)y * 64 + xpx;
            float2 c2 = hv ? *(const float2*)(cbuf + coff) : make_float2(0.f, 0.f);
            float cold[2] = {c2.x, c2.y}, hn[2];
#pragma unroll
            for (int q = 0; q < 2; q++) {
                float I = sigf(acc[0][nt][part * 2 + q] + bi);
                float F = sigf(acc[1][nt][part * 2 + q] + bfv);
                float O = sigf(acc[2][nt][part * 2 + q] + bo);
                float G = tanhf(acc[3][nt][part * 2 + q] + bg);
                float cn = F * cold[q] + I * G;
                cold[q] = cn;
                hn[q] = O * tanhf(cn);
            }
            if (hv) {
                *(float2*)(cbuf + coff) = make_float2(cold[0], cold[1]);
                if (hfout)
                    *(float2*)(hfout + coff) = make_float2(hn[0], hn[1]);
            }
            // pack channel pairs: partner hid^1 lives at lane^4
            float pn0 = __shfl_xor_sync(0xffffffffu, hn[0], 4);
            float pn1 = __shfl_xor_sync(0xffffffffu, hn[1], 4);
            if (((gq & 1) == 0) && hv) {
                const int qp = hid >> 1;
                const size_t ob =
                    (((size_t)b * (HID / 2) + qp) * 2) * 4096 + (size_t)y * 64 + xpx;
                *(uint2*)(hout + ob) = make_uint2(pack_bf(hn[0], pn0), pack_bf(hn[1], pn1));
                *(uint2*)(hout + ob + 4096) =
                    make_uint2(pack_bf(bflo(hn[0]), bflo(pn0)),
                               pack_bf(bflo(hn[1]), bflo(pn1)));
            }
        }
    }
}

// -------------------- host driver -------------------------------------------
extern "C" void kernel_launch(void* const* d_in, const int* in_sizes, int n_in,
                              void* d_out, int out_size) {
    (void)in_sizes; (void)n_in; (void)out_size;
    const float* history = (const float*)d_in[0];
    const float* W0 = (const float*)d_in[2];
    const float* b0 = (const float*)d_in[3];
    const float* W1 = (const float*)d_in[4];
    const float* b1 = (const float*)d_in[5];

    uint32_t *h0p, *h1p, *xp, *wp0, *wp1;
    float *c0, *c1, *h1f;
    cudaGetSymbolAddress((void**)&h0p, g_h0p);
    cudaGetSymbolAddress((void**)&h1p, g_h1p);
    cudaGetSymbolAddress((void**)&xp,  g_xp);
    cudaGetSymbolAddress((void**)&wp0, g_wp0);
    cudaGetSymbolAddress((void**)&wp1, g_wp1);
    cudaGetSymbolAddress((void**)&c0,  g_c0);
    cudaGetSymbolAddress((void**)&c1,  g_c1);
    cudaGetSymbolAddress((void**)&h1f, g_h1f);

    cudaFuncSetAttribute(conv_step<64, 1, 128>,
                         cudaFuncAttributeMaxDynamicSharedMemorySize, SMEM_BYTES);
    cudaFuncSetAttribute(conv_step<64, 6, 12>,
                         cudaFuncAttributeMaxDynamicSharedMemorySize, SMEM_BYTES);

    zero_init_kernel<<<1024, 256>>>();
    xprep_kernel<<<768, 256>>>(history);
    repack_w<<<648, 256>>>(W0, wp0, 128, 129, 8, 0);
    repack_w<<<81, 256>>>(W1, wp1, 12, 140, 1, 1);

    const size_t H0SZ = (size_t)16 * 64 * 2 * 4096;
    const size_t H1SZ = (size_t)16 * 6 * 2 * 4096;

    int pa = 0;
    for (int t = 0; t < TSTEPS; t++) {
        const uint32_t* h0r = h0p + (size_t)pa * H0SZ;
        uint32_t*       h0w = h0p + (size_t)(1 - pa) * H0SZ;
        const uint32_t* h1r = h1p + (size_t)pa * H1SZ;
        uint32_t*       h1w = h1p + (size_t)(1 - pa) * H1SZ;

        conv_step<64, 1, 128><<<dim3(8, 8, 16), 256, SMEM_BYTES>>>(
            h0r, xp + (size_t)t * 16 * 2 * 4096, wp0, b0, c0, h0w, nullptr);

        conv_step<64, 6, 12><<<dim3(8, 1, 16), 256, SMEM_BYTES>>>(
            h0w, h1r, wp1, b1, c1, h1w, h1f);

        pa ^= 1;
    }

    cudaMemcpyAsync(d_out, h1f, (size_t)16 * 12 * 4096 * sizeof(float),
                    cudaMemcpyDeviceToDevice);
}

// round 8
// speedup vs baseline: 1.6791x; 1.6791x over previous
#include <cuda_runtime.h>
#include <cuda_fp16.h>
#include <math.h>
#include <stdint.h>

// ---------------------------------------------------------------------------
// ConvLSTM (2 layers, 12 steps) — tensor-core implicit GEMM, fp16 2-term split.
// w = Wh + Wl (both fp16); acts single fp16. conv = Wh*A + Wl*A (2 MMAs).
// Residual Wh*(a-A) ~ 1.5e-4 rel — inside the 1e-3 gate.
// Activations stored as channel-pair planes: uint32 = {fp16 ch2p | fp16 ch2p+1}.
// Warp tile: 8px x 4 rows x 16 hid x 4 gates (R4 shape, 512 thr, nt=4).
// ---------------------------------------------------------------------------

#define TSTEPS 12
#define NCHUNK 9

__device__ uint32_t g_h0p[2u * 16u * 64u * 4096u];   // h0 pair planes (fp16x2)
__device__ uint32_t g_h1p[2u * 16u * 6u  * 4096u];   // h1 pair planes
__device__ uint32_t g_xp [12u * 16u * 4096u];        // x pair planes per t
__device__ float    g_c0 [16u * 128u * 4096u];
__device__ float    g_c1 [16u * 12u  * 4096u];
__device__ float    g_h1f[16u * 12u * 4096u];        // float h1 (output)
__device__ uint32_t g_wp0[8u * 9u * 9216u];          // frag-packed weights hi/lo
__device__ uint32_t g_wp1[1u * 9u * 9216u];

#define SW_ACT   5824u              // one act chunk: 8 planes * 728 words
#define SW_W_OFF 11648u             // after 2 act buffers
#define SW_W_BUF 9216u
#define SMEM_BYTES ((11648u + 18432u) * 4u)   // 120,320 B

// -------------------- helpers ----------------------------------------------
__device__ __forceinline__ void mma_f16(float* d, const uint32_t* a,
                                        uint32_t b0, uint32_t b1) {
    asm volatile(
        "mma.sync.aligned.m16n8k16.row.col.f32.f16.f16.f32 "
        "{%0,%1,%2,%3}, {%4,%5,%6,%7}, {%8,%9}, {%0,%1,%2,%3};"
        : "+f"(d[0]), "+f"(d[1]), "+f"(d[2]), "+f"(d[3])
        : "r"(a[0]), "r"(a[1]), "r"(a[2]), "r"(a[3]), "r"(b0), "r"(b1));
}
__device__ __forceinline__ uint32_t smaddr(const void* p) {
    return (uint32_t)__cvta_generic_to_shared(p);
}
__device__ __forceinline__ void cpa16(uint32_t dst, const void* src) {
    asm volatile("cp.async.cg.shared.global [%0], [%1], 16;" :: "r"(dst), "l"(src));
}
__device__ __forceinline__ uint32_t pack_hf(float a, float b) {
    __half2 h = __floats2half2_rn(a, b);
    return *(uint32_t*)&h;
}
__device__ __forceinline__ float hflo(float v) {
    return v - __half2float(__float2half_rn(v));
}
__device__ __forceinline__ float sigf(float x) { return 1.f / (1.f + __expf(-x)); }

// -------------------- init kernels -----------------------------------------
__global__ void zero_init_kernel() {
    size_t tid = (size_t)blockIdx.x * blockDim.x + threadIdx.x;
    size_t st  = (size_t)gridDim.x * blockDim.x;
    const size_t nh0 = (size_t)2 * 16 * 64 * 4096;
    const size_t nh1 = (size_t)2 * 16 * 6 * 4096;
    const size_t nc0 = (size_t)16 * 128 * 4096;
    const size_t nc1 = (size_t)16 * 12 * 4096;
    for (size_t i = tid; i < nh0; i += st) g_h0p[i] = 0u;
    for (size_t i = tid; i < nh1; i += st) g_h1p[i] = 0u;
    for (size_t i = tid; i < nc0; i += st) g_c0[i] = 0.f;
    for (size_t i = tid; i < nc1; i += st) g_c1[i] = 0.f;
}

__global__ void xprep_kernel(const float* __restrict__ hist) {
    int n = TSTEPS * 16 * 4096;
    for (int i = blockIdx.x * blockDim.x + threadIdx.x; i < n;
         i += gridDim.x * blockDim.x) {
        int px = i & 4095, b = (i >> 12) & 15, t = i >> 16;
        float v = hist[((size_t)b * TSTEPS + t) * 4096 + px];
        g_xp[((size_t)t * 16 + b) * 4096 + px] = pack_hf(v, 0.f);
    }
}

// Weights -> A-fragment order: [hb][chunk][ ((tap*4+g)*2+s)*128 + lane*4 + r ]
// s=0: hi (fp16 of w), s=1: lo (fp16 of residual).
// reg r: m = lane/4 + (r&1)*8 ; pair = lane%4 + ((r>>1)&1)*4
__global__ void repack_w(const float* __restrict__ W, uint32_t* __restrict__ Wp,
                         int HID, int CIN, int NHB, int layer) {
    int total = NHB * NCHUNK * 9216;
    for (int idx = blockIdx.x * blockDim.x + threadIdx.x; idx < total;
         idx += gridDim.x * blockDim.x) {
        int wrd = idx % 9216, rest = idx / 9216;
        int c = rest % NCHUNK, hb = rest / NCHUNK;
        int r = wrd & 3, lane = (wrd >> 2) & 31, sgt = wrd >> 7;
        int s = sgt & 1, g = (sgt >> 1) & 3, t = sgt >> 3;
        int m  = (lane >> 2) + (r & 1) * 8;
        int pr = (lane & 3) + ((r >> 1) & 1) * 4;
        int p  = c * 8 + pr;
        int hid = hb * 16 + m;
        int k0 = -1, k1 = -1;
        if (layer == 0) {
            if (p < 64)       { k0 = 2 * p + 1; k1 = 2 * p + 2; }
            else if (p == 64) { k0 = 0; }
        } else {
            if (p < 64)      { k0 = 2 * p; k1 = 2 * p + 1; }
            else if (p < 70) { k0 = 128 + 2 * (p - 64); k1 = k0 + 1; }
        }
        float w0 = 0.f, w1 = 0.f;
        if (hid < HID) {
            if (k0 >= 0) w0 = W[((size_t)(g * HID + hid) * CIN + k0) * 9 + t];
            if (k1 >= 0) w1 = W[((size_t)(g * HID + hid) * CIN + k1) * 9 + t];
        }
        Wp[idx] = (s == 0) ? pack_hf(w0, w1) : pack_hf(hflo(w0), hflo(w1));
    }
}

// -------------------- fused conv + LSTM step --------------------------------
// Grid (8 y-tiles, NHB, 16 batch), block 512 = 16 warps (wx 0..7, wy 0..1).
// Warp: 16 hid x 4 gates x 32 px (8-px strip, 4 rows). 64 f32 accs/thread.
template <int NPA, int NPB, int HID>
__global__ __launch_bounds__(512, 1)
void conv_step(const uint32_t* __restrict__ actA,   // [b][NPA][4096]
               const uint32_t* __restrict__ actB,   // [b][NPB][4096]
               const uint32_t* __restrict__ Wg,     // [hb][9][9216]
               const float*    __restrict__ bias,
               float*          __restrict__ cbuf,   // [b][HID][4096]
               uint32_t*       __restrict__ hout,   // [b][HID/2][4096]
               float*          __restrict__ hfout) {
    extern __shared__ uint32_t sm[];
    const int tid = threadIdx.x;
    const int lane = tid & 31, warp = tid >> 5;
    const int tg = lane & 3, gq = lane >> 2;
    const int wx = warp & 7, wy = warp >> 3;
    const int y0 = blockIdx.x * 8;
    const int hb = blockIdx.y;
    const int b  = blockIdx.z;
    const uint32_t* wgm = Wg + (size_t)hb * NCHUNK * 9216;

    // zero halo columns (0..3, 68..71) for all planes, both act buffers
    if (tid < 320) {
        int side = tid & 1, v = tid >> 1;
        int r = v % 10, p = (v / 10) & 7, bfi = v / 80;
        uint32_t* dst = sm + bfi * SW_ACT + p * 728 + r * 72 + (side ? 68 : 0);
        *(uint4*)dst = make_uint4(0, 0, 0, 0);
    }

    float acc[4][4][4];
#pragma unroll
    for (int g = 0; g < 4; g++)
#pragma unroll
        for (int n = 0; n < 4; n++)
#pragma unroll
            for (int r = 0; r < 4; r++) acc[g][n][r] = 0.f;

    auto ldchunk = [&](int c, int bfi) {
#pragma unroll
        for (int k = 0; k < 3; k++) {
            int u = tid + k * 512;               // 1280 uint4: act data
            if (u < 1280) {
                int p = u & 7, rest = u >> 3;
                int r = rest % 10, seg = rest / 10;     // seg: 16 x 4px
                int pair = c * 8 + p;
                int y = y0 + r - 1;
                uint32_t* dst = sm + bfi * SW_ACT + p * 728 + r * 72 + 4 + seg * 4;
                const uint32_t* src = nullptr;
                if ((unsigned)y < 64u) {
                    if (pair < NPA)
                        src = actA + ((size_t)b * NPA + pair) * 4096 + y * 64 + seg * 4;
                    else if (pair < NPA + NPB)
                        src = actB + ((size_t)b * NPB + (pair - NPA)) * 4096 +
                              y * 64 + seg * 4;
                }
                if (src) cpa16(smaddr(dst), src);
                else     *(uint4*)dst = make_uint4(0, 0, 0, 0);
            }
        }
        const uint32_t* wsrc = wgm + (size_t)c * 9216;
        uint32_t* wdst = sm + SW_W_OFF + bfi * SW_W_BUF;
#pragma unroll
        for (int k = 0; k < 5; k++) {
            int u = tid + k * 512;               // 2304 uint4: weights
            if (u < 2304) cpa16(smaddr(wdst + u * 4), wsrc + u * 4);
        }
        asm volatile("cp.async.commit_group;");
    };

    ldchunk(0, 0);

    for (int c = 0; c < NCHUNK; c++) {
        const int bfi = c & 1;
        if (c + 1 < NCHUNK) {
            ldchunk(c + 1, bfi ^ 1);
            asm volatile("cp.async.wait_group 1;");
        } else {
            asm volatile("cp.async.wait_group 0;");
        }
        __syncthreads();

        const uint32_t* ws = sm + SW_W_OFF + bfi * SW_W_BUF;
        const uint32_t* aB = sm + bfi * SW_ACT;

#pragma unroll
        for (int ky = 0; ky < 3; ky++) {
#pragma unroll
            for (int kx = 0; kx < 3; kx++) {
                const int t = ky * 3 + kx;
                const int cb = 4 + wx * 8 + gq + kx - 1;
                uint32_t bh[4][2];
#pragma unroll
                for (int nt = 0; nt < 4; nt++) {
                    int o0 = tg * 728 + (wy * 4 + ky + nt) * 72 + cb;
                    bh[nt][0] = aB[o0]; bh[nt][1] = aB[o0 + 4 * 728];
                }
#pragma unroll
                for (int g = 0; g < 4; g++) {
                    uint4 ah = *(const uint4*)(ws + ((t * 4 + g) * 2 + 0) * 128 + lane * 4);
                    uint4 al = *(const uint4*)(ws + ((t * 4 + g) * 2 + 1) * 128 + lane * 4);
#pragma unroll
                    for (int nt = 0; nt < 4; nt++) {
                        mma_f16(acc[g][nt], (const uint32_t*)&ah, bh[nt][0], bh[nt][1]);
                        mma_f16(acc[g][nt], (const uint32_t*)&al, bh[nt][0], bh[nt][1]);
                    }
                }
            }
        }
        __syncthreads();
    }

    // ---- LSTM epilogue -----------------------------------------------------
    const int xpx = wx * 8 + tg * 2;
#pragma unroll
    for (int part = 0; part < 2; part++) {
        const int hid = hb * 16 + gq + part * 8;
        const bool hv = (hid < HID);
        float bi = 0.f, bfv = 0.f, bo = 0.f, bg = 0.f;
        if (hv) {
            bi = bias[hid]; bfv = bias[HID + hid];
            bo = bias[2 * HID + hid]; bg = bias[3 * HID + hid];
        }
#pragma unroll
        for (int nt = 0; nt < 4; nt++) {
            const int y = y0 + wy * 4 + nt;
            const size_t coff =
                ((size_t)(b * HID + (hv ? hid : 0))) * 4096 + (size_t)y * 64 + xpx;
            float2 c2 = hv ? *(const float2*)(cbuf + coff) : make_float2(0.f, 0.f);
            float cold[2] = {c2.x, c2.y}, hn[2];
#pragma unroll
            for (int q = 0; q < 2; q++) {
                float I = sigf(acc[0][nt][part * 2 + q] + bi);
                float F = sigf(acc[1][nt][part * 2 + q] + bfv);
                float O = sigf(acc[2][nt][part * 2 + q] + bo);
                float G = tanhf(acc[3][nt][part * 2 + q] + bg);
                float cn = F * cold[q] + I * G;
                cold[q] = cn;
                hn[q] = O * tanhf(cn);
            }
            if (hv) {
                *(float2*)(cbuf + coff) = make_float2(cold[0], cold[1]);
                if (hfout)
                    *(float2*)(hfout + coff) = make_float2(hn[0], hn[1]);
            }
            // pack channel pairs: partner hid^1 lives at lane^4
            float pn0 = __shfl_xor_sync(0xffffffffu, hn[0], 4);
            float pn1 = __shfl_xor_sync(0xffffffffu, hn[1], 4);
            if (((gq & 1) == 0) && hv) {
                const int qp = hid >> 1;
                const size_t ob =
                    ((size_t)b * (HID / 2) + qp) * 4096 + (size_t)y * 64 + xpx;
                *(uint2*)(hout + ob) =
                    make_uint2(pack_hf(hn[0], pn0), pack_hf(hn[1], pn1));
            }
        }
    }
}

// -------------------- host driver -------------------------------------------
extern "C" void kernel_launch(void* const* d_in, const int* in_sizes, int n_in,
                              void* d_out, int out_size) {
    (void)in_sizes; (void)n_in; (void)out_size;
    const float* history = (const float*)d_in[0];
    const float* W0 = (const float*)d_in[2];
    const float* b0 = (const float*)d_in[3];
    const float* W1 = (const float*)d_in[4];
    const float* b1 = (const float*)d_in[5];

    uint32_t *h0p, *h1p, *xp, *wp0, *wp1;
    float *c0, *c1, *h1f;
    cudaGetSymbolAddress((void**)&h0p, g_h0p);
    cudaGetSymbolAddress((void**)&h1p, g_h1p);
    cudaGetSymbolAddress((void**)&xp,  g_xp);
    cudaGetSymbolAddress((void**)&wp0, g_wp0);
    cudaGetSymbolAddress((void**)&wp1, g_wp1);
    cudaGetSymbolAddress((void**)&c0,  g_c0);
    cudaGetSymbolAddress((void**)&c1,  g_c1);
    cudaGetSymbolAddress((void**)&h1f, g_h1f);

    cudaFuncSetAttribute(conv_step<64, 1, 128>,
                         cudaFuncAttributeMaxDynamicSharedMemorySize, SMEM_BYTES);
    cudaFuncSetAttribute(conv_step<64, 6, 12>,
                         cudaFuncAttributeMaxDynamicSharedMemorySize, SMEM_BYTES);

    zero_init_kernel<<<1024, 256>>>();
    xprep_kernel<<<768, 256>>>(history);
    repack_w<<<648, 256>>>(W0, wp0, 128, 129, 8, 0);
    repack_w<<<81, 256>>>(W1, wp1, 12, 140, 1, 1);

    const size_t H0SZ = (size_t)16 * 64 * 4096;
    const size_t H1SZ = (size_t)16 * 6 * 4096;

    int pa = 0;
    for (int t = 0; t < TSTEPS; t++) {
        const uint32_t* h0r = h0p + (size_t)pa * H0SZ;
        uint32_t*       h0w = h0p + (size_t)(1 - pa) * H0SZ;
        const uint32_t* h1r = h1p + (size_t)pa * H1SZ;
        uint32_t*       h1w = h1p + (size_t)(1 - pa) * H1SZ;

        conv_step<64, 1, 128><<<dim3(8, 8, 16), 512, SMEM_BYTES>>>(
            h0r, xp + (size_t)t * 16 * 4096, wp0, b0, c0, h0w, nullptr);

        conv_step<64, 6, 12><<<dim3(8, 1, 16), 512, SMEM_BYTES>>>(
            h0w, h1r, wp1, b1, c1, h1w, h1f);

        pa ^= 1;
    }

    cudaMemcpyAsync(d_out, h1f, (size_t)16 * 12 * 4096 * sizeof(float),
                    cudaMemcpyDeviceToDevice);
}

// round 9
// speedup vs baseline: 1.7710x; 1.0547x over previous
#include <cuda_runtime.h>
#include <cuda_fp16.h>
#include <math.h>
#include <stdint.h>

// ---------------------------------------------------------------------------
// ConvLSTM (2 layers, 12 steps) — tensor-core implicit GEMM, fp16 2-term split.
// w = Wh + Wl (both fp16); acts single fp16. conv = Wh*A + Wl*A (2 MMAs).
// R9: 256-thread blocks (y-tile 4 rows), smem 101.9KB -> 2 blocks/SM so
//     epilogue/loads of one block overlap MMAs of the other; MUFU epilogue.
// Activations stored as channel-pair planes: uint32 = {fp16 ch2p | fp16 ch2p+1}.
// ---------------------------------------------------------------------------

#define TSTEPS 12
#define NCHUNK 9

__device__ uint32_t g_h0p[2u * 16u * 64u * 4096u];   // h0 pair planes (fp16x2)
__device__ uint32_t g_h1p[2u * 16u * 6u  * 4096u];   // h1 pair planes
__device__ uint32_t g_xp [12u * 16u * 4096u];        // x pair planes per t
__device__ float    g_c0 [16u * 128u * 4096u];
__device__ float    g_c1 [16u * 12u  * 4096u];
__device__ float    g_h1f[16u * 12u * 4096u];        // float h1 (output)
__device__ uint32_t g_wp0[8u * 9u * 9216u];          // frag-packed weights hi/lo
__device__ uint32_t g_wp1[1u * 9u * 9216u];

#define SW_ACT   3520u              // one act chunk: 8 planes * 440 words
#define SW_W_OFF 7040u              // after 2 act buffers
#define SW_W_BUF 9216u
#define SMEM_BYTES ((7040u + 18432u) * 4u)   // 101,888 B -> 2 blocks/SM

// -------------------- helpers ----------------------------------------------
__device__ __forceinline__ void mma_f16(float* d, const uint32_t* a,
                                        uint32_t b0, uint32_t b1) {
    asm volatile(
        "mma.sync.aligned.m16n8k16.row.col.f32.f16.f16.f32 "
        "{%0,%1,%2,%3}, {%4,%5,%6,%7}, {%8,%9}, {%0,%1,%2,%3};"
        : "+f"(d[0]), "+f"(d[1]), "+f"(d[2]), "+f"(d[3])
        : "r"(a[0]), "r"(a[1]), "r"(a[2]), "r"(a[3]), "r"(b0), "r"(b1));
}
__device__ __forceinline__ uint32_t smaddr(const void* p) {
    return (uint32_t)__cvta_generic_to_shared(p);
}
__device__ __forceinline__ void cpa16(uint32_t dst, const void* src) {
    asm volatile("cp.async.cg.shared.global [%0], [%1], 16;" :: "r"(dst), "l"(src));
}
__device__ __forceinline__ uint32_t pack_hf(float a, float b) {
    __half2 h = __floats2half2_rn(a, b);
    return *(uint32_t*)&h;
}
__device__ __forceinline__ float hflo(float v) {
    return v - __half2float(__float2half_rn(v));
}
__device__ __forceinline__ float ex2f(float x) {
    float y; asm("ex2.approx.f32 %0, %1;" : "=f"(y) : "f"(x)); return y;
}
__device__ __forceinline__ float rcpf(float x) {
    float y; asm("rcp.approx.f32 %0, %1;" : "=f"(y) : "f"(x)); return y;
}
__device__ __forceinline__ float sigf(float x) {
    return rcpf(1.f + ex2f(-1.44269504f * x));
}
__device__ __forceinline__ float tanh_fast(float x) {
    return 2.f * rcpf(1.f + ex2f(-2.88539008f * x)) - 1.f;
}

// -------------------- init kernels -----------------------------------------
__global__ void zero_init_kernel() {
    size_t tid = (size_t)blockIdx.x * blockDim.x + threadIdx.x;
    size_t st  = (size_t)gridDim.x * blockDim.x;
    const size_t nh0 = (size_t)2 * 16 * 64 * 4096;
    const size_t nh1 = (size_t)2 * 16 * 6 * 4096;
    const size_t nc0 = (size_t)16 * 128 * 4096;
    const size_t nc1 = (size_t)16 * 12 * 4096;
    for (size_t i = tid; i < nh0; i += st) g_h0p[i] = 0u;
    for (size_t i = tid; i < nh1; i += st) g_h1p[i] = 0u;
    for (size_t i = tid; i < nc0; i += st) g_c0[i] = 0.f;
    for (size_t i = tid; i < nc1; i += st) g_c1[i] = 0.f;
}

__global__ void xprep_kernel(const float* __restrict__ hist) {
    int n = TSTEPS * 16 * 4096;
    for (int i = blockIdx.x * blockDim.x + threadIdx.x; i < n;
         i += gridDim.x * blockDim.x) {
        int px = i & 4095, b = (i >> 12) & 15, t = i >> 16;
        float v = hist[((size_t)b * TSTEPS + t) * 4096 + px];
        g_xp[((size_t)t * 16 + b) * 4096 + px] = pack_hf(v, 0.f);
    }
}

// Weights -> A-fragment order: [hb][chunk][ ((tap*4+g)*2+s)*128 + lane*4 + r ]
// s=0: hi (fp16 of w), s=1: lo (fp16 of residual).
// reg r: m = lane/4 + (r&1)*8 ; pair = lane%4 + ((r>>1)&1)*4
__global__ void repack_w(const float* __restrict__ W, uint32_t* __restrict__ Wp,
                         int HID, int CIN, int NHB, int layer) {
    int total = NHB * NCHUNK * 9216;
    for (int idx = blockIdx.x * blockDim.x + threadIdx.x; idx < total;
         idx += gridDim.x * blockDim.x) {
        int wrd = idx % 9216, rest = idx / 9216;
        int c = rest % NCHUNK, hb = rest / NCHUNK;
        int r = wrd & 3, lane = (wrd >> 2) & 31, sgt = wrd >> 7;
        int s = sgt & 1, g = (sgt >> 1) & 3, t = sgt >> 3;
        int m  = (lane >> 2) + (r & 1) * 8;
        int pr = (lane & 3) + ((r >> 1) & 1) * 4;
        int p  = c * 8 + pr;
        int hid = hb * 16 + m;
        int k0 = -1, k1 = -1;
        if (layer == 0) {
            if (p < 64)       { k0 = 2 * p + 1; k1 = 2 * p + 2; }
            else if (p == 64) { k0 = 0; }
        } else {
            if (p < 64)      { k0 = 2 * p; k1 = 2 * p + 1; }
            else if (p < 70) { k0 = 128 + 2 * (p - 64); k1 = k0 + 1; }
        }
        float w0 = 0.f, w1 = 0.f;
        if (hid < HID) {
            if (k0 >= 0) w0 = W[((size_t)(g * HID + hid) * CIN + k0) * 9 + t];
            if (k1 >= 0) w1 = W[((size_t)(g * HID + hid) * CIN + k1) * 9 + t];
        }
        Wp[idx] = (s == 0) ? pack_hf(w0, w1) : pack_hf(hflo(w0), hflo(w1));
    }
}

// -------------------- fused conv + LSTM step --------------------------------
// Grid (16 y-tiles, NHB, 16 batch), block 256 = 8 warps (wx 0..7).
// Warp: 16 hid x 4 gates x 32 px (8-px strip, 4 rows). 64 f32 accs/thread.
template <int NPA, int NPB, int HID>
__global__ __launch_bounds__(256, 2)
void conv_step(const uint32_t* __restrict__ actA,   // [b][NPA][4096]
               const uint32_t* __restrict__ actB,   // [b][NPB][4096]
               const uint32_t* __restrict__ Wg,     // [hb][9][9216]
               const float*    __restrict__ bias,
               float*          __restrict__ cbuf,   // [b][HID][4096]
               uint32_t*       __restrict__ hout,   // [b][HID/2][4096]
               float*          __restrict__ hfout) {
    extern __shared__ uint32_t sm[];
    const int tid = threadIdx.x;
    const int lane = tid & 31, warp = tid >> 5;
    const int tg = lane & 3, gq = lane >> 2;
    const int wx = warp;                 // 0..7 (8-px strip)
    const int y0 = blockIdx.x * 4;
    const int hb = blockIdx.y;
    const int b  = blockIdx.z;
    const uint32_t* wgm = Wg + (size_t)hb * NCHUNK * 9216;

    // zero halo columns (words 0..3 / 68..71) for all planes, both act buffers
    if (tid < 192) {
        int side = tid & 1, v = tid >> 1;          // v 0..95
        int r = v % 6, p = (v / 6) & 7, bfi = v / 48;
        uint32_t* dst = sm + bfi * SW_ACT + p * 440 + r * 72 + (side ? 68 : 0);
        *(uint4*)dst = make_uint4(0, 0, 0, 0);
    }

    float acc[4][4][4];
#pragma unroll
    for (int g = 0; g < 4; g++)
#pragma unroll
        for (int n = 0; n < 4; n++)
#pragma unroll
            for (int r = 0; r < 4; r++) acc[g][n][r] = 0.f;

    auto ldchunk = [&](int c, int bfi) {
#pragma unroll
        for (int k = 0; k < 3; k++) {
            int u = tid + k * 256;               // 768 uint4: act data
            if (u < 768) {
                int p = u & 7, rest = u >> 3;    // rest 0..95
                int r = rest % 6, seg = rest / 6;       // seg: 16 x 4px
                int pair = c * 8 + p;
                int y = y0 + r - 1;
                uint32_t* dst = sm + bfi * SW_ACT + p * 440 + r * 72 + 4 + seg * 4;
                const uint32_t* src = nullptr;
                if ((unsigned)y < 64u) {
                    if (pair < NPA)
                        src = actA + ((size_t)b * NPA + pair) * 4096 + y * 64 + seg * 4;
                    else if (pair < NPA + NPB)
                        src = actB + ((size_t)b * NPB + (pair - NPA)) * 4096 +
                              y * 64 + seg * 4;
                }
                if (src) cpa16(smaddr(dst), src);
                else     *(uint4*)dst = make_uint4(0, 0, 0, 0);
            }
        }
        const uint32_t* wsrc = wgm + (size_t)c * 9216;
        uint32_t* wdst = sm + SW_W_OFF + bfi * SW_W_BUF;
#pragma unroll
        for (int k = 0; k < 9; k++) {
            int u = tid + k * 256;               // 2304 uint4: weights
            cpa16(smaddr(wdst + u * 4), wsrc + u * 4);
        }
        asm volatile("cp.async.commit_group;");
    };

    ldchunk(0, 0);

    for (int c = 0; c < NCHUNK; c++) {
        const int bfi = c & 1;
        if (c + 1 < NCHUNK) {
            ldchunk(c + 1, bfi ^ 1);
            asm volatile("cp.async.wait_group 1;");
        } else {
            asm volatile("cp.async.wait_group 0;");
        }
        __syncthreads();

        const uint32_t* ws = sm + SW_W_OFF + bfi * SW_W_BUF;
        const uint32_t* aB = sm + bfi * SW_ACT;

#pragma unroll
        for (int ky = 0; ky < 3; ky++) {
#pragma unroll
            for (int kx = 0; kx < 3; kx++) {
                const int t = ky * 3 + kx;
                const int cb = 4 + wx * 8 + gq + kx - 1;
                uint32_t bh[4][2];
#pragma unroll
                for (int nt = 0; nt < 4; nt++) {
                    int o0 = tg * 440 + (ky + nt) * 72 + cb;
                    bh[nt][0] = aB[o0]; bh[nt][1] = aB[o0 + 4 * 440];
                }
#pragma unroll
                for (int g = 0; g < 4; g++) {
                    uint4 ah = *(const uint4*)(ws + ((t * 4 + g) * 2 + 0) * 128 + lane * 4);
                    uint4 al = *(const uint4*)(ws + ((t * 4 + g) * 2 + 1) * 128 + lane * 4);
#pragma unroll
                    for (int nt = 0; nt < 4; nt++) {
                        mma_f16(acc[g][nt], (const uint32_t*)&ah, bh[nt][0], bh[nt][1]);
                        mma_f16(acc[g][nt], (const uint32_t*)&al, bh[nt][0], bh[nt][1]);
                    }
                }
            }
        }
        __syncthreads();
    }

    // ---- LSTM epilogue -----------------------------------------------------
    const int xpx = wx * 8 + tg * 2;
#pragma unroll
    for (int part = 0; part < 2; part++) {
        const int hid = hb * 16 + gq + part * 8;
        const bool hv = (hid < HID);
        float bi = 0.f, bfv = 0.f, bo = 0.f, bg = 0.f;
        if (hv) {
            bi = bias[hid]; bfv = bias[HID + hid];
            bo = bias[2 * HID + hid]; bg = bias[3 * HID + hid];
        }
#pragma unroll
        for (int nt = 0; nt < 4; nt++) {
            const int y = y0 + nt;
            const size_t coff =
                ((size_t)(b * HID + (hv ? hid : 0))) * 4096 + (size_t)y * 64 + xpx;
            float2 c2 = hv ? *(const float2*)(cbuf + coff) : make_float2(0.f, 0.f);
            float cold[2] = {c2.x, c2.y}, hn[2];
#pragma unroll
            for (int q = 0; q < 2; q++) {
                float I = sigf(acc[0][nt][part * 2 + q] + bi);
                float F = sigf(acc[1][nt][part * 2 + q] + bfv);
                float O = sigf(acc[2][nt][part * 2 + q] + bo);
                float G = tanh_fast(acc[3][nt][part * 2 + q] + bg);
                float cn = F * cold[q] + I * G;
                cold[q] = cn;
                hn[q] = O * tanh_fast(cn);
            }
            if (hv) {
                *(float2*)(cbuf + coff) = make_float2(cold[0], cold[1]);
                if (hfout)
                    *(float2*)(hfout + coff) = make_float2(hn[0], hn[1]);
            }
            // pack channel pairs: partner hid^1 lives at lane^4
            float pn0 = __shfl_xor_sync(0xffffffffu, hn[0], 4);
            float pn1 = __shfl_xor_sync(0xffffffffu, hn[1], 4);
            if (((gq & 1) == 0) && hv) {
                const int qp = hid >> 1;
                const size_t ob =
                    ((size_t)b * (HID / 2) + qp) * 4096 + (size_t)y * 64 + xpx;
                *(uint2*)(hout + ob) =
                    make_uint2(pack_hf(hn[0], pn0), pack_hf(hn[1], pn1));
            }
        }
    }
}

// -------------------- host driver -------------------------------------------
extern "C" void kernel_launch(void* const* d_in, const int* in_sizes, int n_in,
                              void* d_out, int out_size) {
    (void)in_sizes; (void)n_in; (void)out_size;
    const float* history = (const float*)d_in[0];
    const float* W0 = (const float*)d_in[2];
    const float* b0 = (const float*)d_in[3];
    const float* W1 = (const float*)d_in[4];
    const float* b1 = (const float*)d_in[5];

    uint32_t *h0p, *h1p, *xp, *wp0, *wp1;
    float *c0, *c1, *h1f;
    cudaGetSymbolAddress((void**)&h0p, g_h0p);
    cudaGetSymbolAddress((void**)&h1p, g_h1p);
    cudaGetSymbolAddress((void**)&xp,  g_xp);
    cudaGetSymbolAddress((void**)&wp0, g_wp0);
    cudaGetSymbolAddress((void**)&wp1, g_wp1);
    cudaGetSymbolAddress((void**)&c0,  g_c0);
    cudaGetSymbolAddress((void**)&c1,  g_c1);
    cudaGetSymbolAddress((void**)&h1f, g_h1f);

    cudaFuncSetAttribute(conv_step<64, 1, 128>,
                         cudaFuncAttributeMaxDynamicSharedMemorySize, SMEM_BYTES);
    cudaFuncSetAttribute(conv_step<64, 6, 12>,
                         cudaFuncAttributeMaxDynamicSharedMemorySize, SMEM_BYTES);

    zero_init_kernel<<<1024, 256>>>();
    xprep_kernel<<<768, 256>>>(history);
    repack_w<<<648, 256>>>(W0, wp0, 128, 129, 8, 0);
    repack_w<<<81, 256>>>(W1, wp1, 12, 140, 1, 1);

    const size_t H0SZ = (size_t)16 * 64 * 4096;
    const size_t H1SZ = (size_t)16 * 6 * 4096;

    int pa = 0;
    for (int t = 0; t < TSTEPS; t++) {
        const uint32_t* h0r = h0p + (size_t)pa * H0SZ;
        uint32_t*       h0w = h0p + (size_t)(1 - pa) * H0SZ;
        const uint32_t* h1r = h1p + (size_t)pa * H1SZ;
        uint32_t*       h1w = h1p + (size_t)(1 - pa) * H1SZ;

        conv_step<64, 1, 128><<<dim3(16, 8, 16), 256, SMEM_BYTES>>>(
            h0r, xp + (size_t)t * 16 * 4096, wp0, b0, c0, h0w, nullptr);

        conv_step<64, 6, 12><<<dim3(16, 1, 16), 256, SMEM_BYTES>>>(
            h0w, h1r, wp1, b1, c1, h1w, h1f);

        pa ^= 1;
    }

    cudaMemcpyAsync(d_out, h1f, (size_t)16 * 12 * 4096 * sizeof(float),
                    cudaMemcpyDeviceToDevice);
}

// round 10
// speedup vs baseline: 1.8162x; 1.0255x over previous
#include <cuda_runtime.h>
#include <cuda_fp16.h>
#include <math.h>
#include <stdint.h>

// ---------------------------------------------------------------------------
// ConvLSTM (2 layers, 12 steps) — tensor-core implicit GEMM, fp16 2-term split.
// w = Wh + Wl (both fp16); acts single fp16. conv = Wh*A + Wl*A (2 MMAs).
// R10: weights are NOT staged through smem. Each warp LDG.128s its A-fragments
//      straight from the frag-ordered global array (L1-cached, deduped).
//      cp.async issue pressure drops 4x -> MMA-issue-bound. smem 28KB.
// Activations stored as channel-pair planes: uint32 = {fp16 ch2p | fp16 ch2p+1}.
// ---------------------------------------------------------------------------

#define TSTEPS 12
#define NCHUNK 9

__device__ uint32_t g_h0p[2u * 16u * 64u * 4096u];   // h0 pair planes (fp16x2)
__device__ uint32_t g_h1p[2u * 16u * 6u  * 4096u];   // h1 pair planes
__device__ uint32_t g_xp [12u * 16u * 4096u];        // x pair planes per t
__device__ float    g_c0 [16u * 128u * 4096u];
__device__ float    g_c1 [16u * 12u  * 4096u];
__device__ float    g_h1f[16u * 12u * 4096u];        // float h1 (output)
__device__ uint32_t g_wp0[8u * 9u * 9216u];          // frag-packed weights hi/lo
__device__ uint32_t g_wp1[1u * 9u * 9216u];

#define SW_ACT   3520u              // one act chunk: 8 planes * 440 words
#define SMEM_BYTES (2u * SW_ACT * 4u)        // 28,160 B

// -------------------- helpers ----------------------------------------------
__device__ __forceinline__ void mma_f16(float* d, const uint32_t* a,
                                        uint32_t b0, uint32_t b1) {
    asm volatile(
        "mma.sync.aligned.m16n8k16.row.col.f32.f16.f16.f32 "
        "{%0,%1,%2,%3}, {%4,%5,%6,%7}, {%8,%9}, {%0,%1,%2,%3};"
        : "+f"(d[0]), "+f"(d[1]), "+f"(d[2]), "+f"(d[3])
        : "r"(a[0]), "r"(a[1]), "r"(a[2]), "r"(a[3]), "r"(b0), "r"(b1));
}
__device__ __forceinline__ uint32_t smaddr(const void* p) {
    return (uint32_t)__cvta_generic_to_shared(p);
}
__device__ __forceinline__ void cpa16(uint32_t dst, const void* src) {
    asm volatile("cp.async.cg.shared.global [%0], [%1], 16;" :: "r"(dst), "l"(src));
}
__device__ __forceinline__ uint32_t pack_hf(float a, float b) {
    __half2 h = __floats2half2_rn(a, b);
    return *(uint32_t*)&h;
}
__device__ __forceinline__ float hflo(float v) {
    return v - __half2float(__float2half_rn(v));
}
__device__ __forceinline__ float ex2f(float x) {
    float y; asm("ex2.approx.f32 %0, %1;" : "=f"(y) : "f"(x)); return y;
}
__device__ __forceinline__ float rcpf(float x) {
    float y; asm("rcp.approx.f32 %0, %1;" : "=f"(y) : "f"(x)); return y;
}
__device__ __forceinline__ float sigf(float x) {
    return rcpf(1.f + ex2f(-1.44269504f * x));
}
__device__ __forceinline__ float tanh_fast(float x) {
    return 2.f * rcpf(1.f + ex2f(-2.88539008f * x)) - 1.f;
}

// -------------------- init kernels -----------------------------------------
__global__ void zero_init_kernel() {
    size_t tid = (size_t)blockIdx.x * blockDim.x + threadIdx.x;
    size_t st  = (size_t)gridDim.x * blockDim.x;
    const size_t nh0 = (size_t)2 * 16 * 64 * 4096;
    const size_t nh1 = (size_t)2 * 16 * 6 * 4096;
    const size_t nc0 = (size_t)16 * 128 * 4096;
    const size_t nc1 = (size_t)16 * 12 * 4096;
    for (size_t i = tid; i < nh0; i += st) g_h0p[i] = 0u;
    for (size_t i = tid; i < nh1; i += st) g_h1p[i] = 0u;
    for (size_t i = tid; i < nc0; i += st) g_c0[i] = 0.f;
    for (size_t i = tid; i < nc1; i += st) g_c1[i] = 0.f;
}

__global__ void xprep_kernel(const float* __restrict__ hist) {
    int n = TSTEPS * 16 * 4096;
    for (int i = blockIdx.x * blockDim.x + threadIdx.x; i < n;
         i += gridDim.x * blockDim.x) {
        int px = i & 4095, b = (i >> 12) & 15, t = i >> 16;
        float v = hist[((size_t)b * TSTEPS + t) * 4096 + px];
        g_xp[((size_t)t * 16 + b) * 4096 + px] = pack_hf(v, 0.f);
    }
}

// Weights -> A-fragment order: [hb][chunk][ ((tap*4+g)*2+s)*128 + lane*4 + r ]
// s=0: hi (fp16 of w), s=1: lo (fp16 of residual).
// reg r: m = lane/4 + (r&1)*8 ; pair = lane%4 + ((r>>1)&1)*4
__global__ void repack_w(const float* __restrict__ W, uint32_t* __restrict__ Wp,
                         int HID, int CIN, int NHB, int layer) {
    int total = NHB * NCHUNK * 9216;
    for (int idx = blockIdx.x * blockDim.x + threadIdx.x; idx < total;
         idx += gridDim.x * blockDim.x) {
        int wrd = idx % 9216, rest = idx / 9216;
        int c = rest % NCHUNK, hb = rest / NCHUNK;
        int r = wrd & 3, lane = (wrd >> 2) & 31, sgt = wrd >> 7;
        int s = sgt & 1, g = (sgt >> 1) & 3, t = sgt >> 3;
        int m  = (lane >> 2) + (r & 1) * 8;
        int pr = (lane & 3) + ((r >> 1) & 1) * 4;
        int p  = c * 8 + pr;
        int hid = hb * 16 + m;
        int k0 = -1, k1 = -1;
        if (layer == 0) {
            if (p < 64)       { k0 = 2 * p + 1; k1 = 2 * p + 2; }
            else if (p == 64) { k0 = 0; }
        } else {
            if (p < 64)      { k0 = 2 * p; k1 = 2 * p + 1; }
            else if (p < 70) { k0 = 128 + 2 * (p - 64); k1 = k0 + 1; }
        }
        float w0 = 0.f, w1 = 0.f;
        if (hid < HID) {
            if (k0 >= 0) w0 = W[((size_t)(g * HID + hid) * CIN + k0) * 9 + t];
            if (k1 >= 0) w1 = W[((size_t)(g * HID + hid) * CIN + k1) * 9 + t];
        }
        Wp[idx] = (s == 0) ? pack_hf(w0, w1) : pack_hf(hflo(w0), hflo(w1));
    }
}

// -------------------- fused conv + LSTM step --------------------------------
// Grid (16 y-tiles, NHB, 16 batch), block 256 = 8 warps (wx 0..7).
// Warp: 16 hid x 4 gates x 32 px (8-px strip, 4 rows). 64 f32 accs/thread.
// Weights: per-tap LDG.128 fragments straight from global (L1-cached).
template <int NPA, int NPB, int HID>
__global__ __launch_bounds__(256, 2)
void conv_step(const uint32_t* __restrict__ actA,   // [b][NPA][4096]
               const uint32_t* __restrict__ actB,   // [b][NPB][4096]
               const uint32_t* __restrict__ Wg,     // [hb][9][9216] frag order
               const float*    __restrict__ bias,
               float*          __restrict__ cbuf,   // [b][HID][4096]
               uint32_t*       __restrict__ hout,   // [b][HID/2][4096]
               float*          __restrict__ hfout) {
    extern __shared__ uint32_t sm[];
    const int tid = threadIdx.x;
    const int lane = tid & 31, warp = tid >> 5;
    const int tg = lane & 3, gq = lane >> 2;
    const int wx = warp;                 // 0..7 (8-px strip)
    const int y0 = blockIdx.x * 4;
    const int hb = blockIdx.y;
    const int b  = blockIdx.z;
    const uint32_t* wgm = Wg + (size_t)hb * NCHUNK * 9216 + lane * 4;

    // zero halo columns (words 0..3 / 68..71) for all planes, both act buffers
    if (tid < 192) {
        int side = tid & 1, v = tid >> 1;          // v 0..95
        int r = v % 6, p = (v / 6) & 7, bfi = v / 48;
        uint32_t* dst = sm + bfi * SW_ACT + p * 440 + r * 72 + (side ? 68 : 0);
        *(uint4*)dst = make_uint4(0, 0, 0, 0);
    }

    float acc[4][4][4];
#pragma unroll
    for (int g = 0; g < 4; g++)
#pragma unroll
        for (int n = 0; n < 4; n++)
#pragma unroll
            for (int r = 0; r < 4; r++) acc[g][n][r] = 0.f;

    auto ldchunk = [&](int c, int bfi) {
#pragma unroll
        for (int k = 0; k < 3; k++) {
            int u = tid + k * 256;               // 768 uint4: act data
            int p = u & 7, rest = u >> 3;        // rest 0..95
            int r = rest % 6, seg = rest / 6;    // seg: 16 x 4px
            int pair = c * 8 + p;
            int y = y0 + r - 1;
            uint32_t* dst = sm + bfi * SW_ACT + p * 440 + r * 72 + 4 + seg * 4;
            const uint32_t* src = nullptr;
            if ((unsigned)y < 64u) {
                if (pair < NPA)
                    src = actA + ((size_t)b * NPA + pair) * 4096 + y * 64 + seg * 4;
                else if (pair < NPA + NPB)
                    src = actB + ((size_t)b * NPB + (pair - NPA)) * 4096 +
                          y * 64 + seg * 4;
            }
            if (src) cpa16(smaddr(dst), src);
            else     *(uint4*)dst = make_uint4(0, 0, 0, 0);
        }
        asm volatile("cp.async.commit_group;");
    };

    ldchunk(0, 0);

    for (int c = 0; c < NCHUNK; c++) {
        const int bfi = c & 1;
        if (c + 1 < NCHUNK) {
            ldchunk(c + 1, bfi ^ 1);
            asm volatile("cp.async.wait_group 1;");
        } else {
            asm volatile("cp.async.wait_group 0;");
        }
        __syncthreads();

        const uint32_t* aB = sm + bfi * SW_ACT;
        const uint32_t* wc = wgm + (size_t)c * 9216;

#pragma unroll
        for (int ky = 0; ky < 3; ky++) {
#pragma unroll
            for (int kx = 0; kx < 3; kx++) {
                const int t = ky * 3 + kx;
                const int cb = 4 + wx * 8 + gq + kx - 1;
                // stage all weight fragments for this tap (8 x LDG.128, L1-hot)
                uint4 ah[4], al[4];
#pragma unroll
                for (int g = 0; g < 4; g++) {
                    ah[g] = __ldg((const uint4*)(wc + ((t * 4 + g) * 2 + 0) * 128));
                    al[g] = __ldg((const uint4*)(wc + ((t * 4 + g) * 2 + 1) * 128));
                }
                uint32_t bh[4][2];
#pragma unroll
                for (int nt = 0; nt < 4; nt++) {
                    int o0 = tg * 440 + (ky + nt) * 72 + cb;
                    bh[nt][0] = aB[o0]; bh[nt][1] = aB[o0 + 4 * 440];
                }
#pragma unroll
                for (int g = 0; g < 4; g++) {
#pragma unroll
                    for (int nt = 0; nt < 4; nt++) {
                        mma_f16(acc[g][nt], (const uint32_t*)&ah[g], bh[nt][0], bh[nt][1]);
                        mma_f16(acc[g][nt], (const uint32_t*)&al[g], bh[nt][0], bh[nt][1]);
                    }
                }
            }
        }
        __syncthreads();
    }

    // ---- LSTM epilogue -----------------------------------------------------
    const int xpx = wx * 8 + tg * 2;
#pragma unroll
    for (int part = 0; part < 2; part++) {
        const int hid = hb * 16 + gq + part * 8;
        const bool hv = (hid < HID);
        float bi = 0.f, bfv = 0.f, bo = 0.f, bg = 0.f;
        if (hv) {
            bi = bias[hid]; bfv = bias[HID + hid];
            bo = bias[2 * HID + hid]; bg = bias[3 * HID + hid];
        }
#pragma unroll
        for (int nt = 0; nt < 4; nt++) {
            const int y = y0 + nt;
            const size_t coff =
                ((size_t)(b * HID + (hv ? hid : 0))) * 4096 + (size_t)y * 64 + xpx;
            float2 c2 = hv ? *(const float2*)(cbuf + coff) : make_float2(0.f, 0.f);
            float cold[2] = {c2.x, c2.y}, hn[2];
#pragma unroll
            for (int q = 0; q < 2; q++) {
                float I = sigf(acc[0][nt][part * 2 + q] + bi);
                float F = sigf(acc[1][nt][part * 2 + q] + bfv);
                float O = sigf(acc[2][nt][part * 2 + q] + bo);
                float G = tanh_fast(acc[3][nt][part * 2 + q] + bg);
                float cn = F * cold[q] + I * G;
                cold[q] = cn;
                hn[q] = O * tanh_fast(cn);
            }
            if (hv) {
                *(float2*)(cbuf + coff) = make_float2(cold[0], cold[1]);
                if (hfout)
                    *(float2*)(hfout + coff) = make_float2(hn[0], hn[1]);
            }
            // pack channel pairs: partner hid^1 lives at lane^4
            float pn0 = __shfl_xor_sync(0xffffffffu, hn[0], 4);
            float pn1 = __shfl_xor_sync(0xffffffffu, hn[1], 4);
            if (((gq & 1) == 0) && hv) {
                const int qp = hid >> 1;
                const size_t ob =
                    ((size_t)b * (HID / 2) + qp) * 4096 + (size_t)y * 64 + xpx;
                *(uint2*)(hout + ob) =
                    make_uint2(pack_hf(hn[0], pn0), pack_hf(hn[1], pn1));
            }
        }
    }
}

// -------------------- host driver -------------------------------------------
extern "C" void kernel_launch(void* const* d_in, const int* in_sizes, int n_in,
                              void* d_out, int out_size) {
    (void)in_sizes; (void)n_in; (void)out_size;
    const float* history = (const float*)d_in[0];
    const float* W0 = (const float*)d_in[2];
    const float* b0 = (const float*)d_in[3];
    const float* W1 = (const float*)d_in[4];
    const float* b1 = (const float*)d_in[5];

    uint32_t *h0p, *h1p, *xp, *wp0, *wp1;
    float *c0, *c1, *h1f;
    cudaGetSymbolAddress((void**)&h0p, g_h0p);
    cudaGetSymbolAddress((void**)&h1p, g_h1p);
    cudaGetSymbolAddress((void**)&xp,  g_xp);
    cudaGetSymbolAddress((void**)&wp0, g_wp0);
    cudaGetSymbolAddress((void**)&wp1, g_wp1);
    cudaGetSymbolAddress((void**)&c0,  g_c0);
    cudaGetSymbolAddress((void**)&c1,  g_c1);
    cudaGetSymbolAddress((void**)&h1f, g_h1f);

    zero_init_kernel<<<1024, 256>>>();
    xprep_kernel<<<768, 256>>>(history);
    repack_w<<<648, 256>>>(W0, wp0, 128, 129, 8, 0);
    repack_w<<<81, 256>>>(W1, wp1, 12, 140, 1, 1);

    const size_t H0SZ = (size_t)16 * 64 * 4096;
    const size_t H1SZ = (size_t)16 * 6 * 4096;

    int pa = 0;
    for (int t = 0; t < TSTEPS; t++) {
        const uint32_t* h0r = h0p + (size_t)pa * H0SZ;
        uint32_t*       h0w = h0p + (size_t)(1 - pa) * H0SZ;
        const uint32_t* h1r = h1p + (size_t)pa * H1SZ;
        uint32_t*       h1w = h1p + (size_t)(1 - pa) * H1SZ;

        conv_step<64, 1, 128><<<dim3(16, 8, 16), 256, SMEM_BYTES>>>(
            h0r, xp + (size_t)t * 16 * 4096, wp0, b0, c0, h0w, nullptr);

        conv_step<64, 6, 12><<<dim3(16, 1, 16), 256, SMEM_BYTES>>>(
            h0w, h1r, wp1, b1, c1, h1w, h1f);

        pa ^= 1;
    }

    cudaMemcpyAsync(d_out, h1f, (size_t)16 * 12 * 4096 * sizeof(float),
                    cudaMemcpyDeviceToDevice);
}

// round 11
// speedup vs baseline: 2.9483x; 1.6233x over previous
#include <cuda_runtime.h>
#include <cuda_fp16.h>
#include <math.h>
#include <stdint.h>

// ---------------------------------------------------------------------------
// ConvLSTM (2 layers, 12 steps) — tensor-core implicit GEMM, pure fp16.
// R11: single fp16 MMA per fragment (weight-lo term dropped; rel_err budget
//      ~4e-4 vs 1e-3 gate). MMA count halves vs R10 -> HMMA roofline halves.
// Weights LDG.128'd straight from frag-ordered global (L1-hot, no smem stage).
// Activations stored as channel-pair planes: uint32 = {fp16 ch2p | fp16 ch2p+1}.
// ---------------------------------------------------------------------------

#define TSTEPS 12
#define NCHUNK 9

__device__ uint32_t g_h0p[2u * 16u * 64u * 4096u];   // h0 pair planes (fp16x2)
__device__ uint32_t g_h1p[2u * 16u * 6u  * 4096u];   // h1 pair planes
__device__ uint32_t g_xp [12u * 16u * 4096u];        // x pair planes per t
__device__ float    g_c0 [16u * 128u * 4096u];
__device__ float    g_c1 [16u * 12u  * 4096u];
__device__ float    g_h1f[16u * 12u * 4096u];        // float h1 (output)
__device__ uint32_t g_wp0[8u * 9u * 4608u];          // frag-packed fp16 weights
__device__ uint32_t g_wp1[1u * 9u * 4608u];

#define SW_ACT   3520u              // one act chunk: 8 planes * 440 words
#define SMEM_BYTES (2u * SW_ACT * 4u)        // 28,160 B

// -------------------- helpers ----------------------------------------------
__device__ __forceinline__ void mma_f16(float* d, const uint32_t* a,
                                        uint32_t b0, uint32_t b1) {
    asm volatile(
        "mma.sync.aligned.m16n8k16.row.col.f32.f16.f16.f32 "
        "{%0,%1,%2,%3}, {%4,%5,%6,%7}, {%8,%9}, {%0,%1,%2,%3};"
        : "+f"(d[0]), "+f"(d[1]), "+f"(d[2]), "+f"(d[3])
        : "r"(a[0]), "r"(a[1]), "r"(a[2]), "r"(a[3]), "r"(b0), "r"(b1));
}
__device__ __forceinline__ uint32_t smaddr(const void* p) {
    return (uint32_t)__cvta_generic_to_shared(p);
}
__device__ __forceinline__ void cpa16(uint32_t dst, const void* src) {
    asm volatile("cp.async.cg.shared.global [%0], [%1], 16;" :: "r"(dst), "l"(src));
}
__device__ __forceinline__ uint32_t pack_hf(float a, float b) {
    __half2 h = __floats2half2_rn(a, b);
    return *(uint32_t*)&h;
}
__device__ __forceinline__ float ex2f(float x) {
    float y; asm("ex2.approx.f32 %0, %1;" : "=f"(y) : "f"(x)); return y;
}
__device__ __forceinline__ float rcpf(float x) {
    float y; asm("rcp.approx.f32 %0, %1;" : "=f"(y) : "f"(x)); return y;
}
__device__ __forceinline__ float sigf(float x) {
    return rcpf(1.f + ex2f(-1.44269504f * x));
}
__device__ __forceinline__ float tanh_fast(float x) {
    return 2.f * rcpf(1.f + ex2f(-2.88539008f * x)) - 1.f;
}

// -------------------- init kernels -----------------------------------------
__global__ void zero_init_kernel() {
    size_t tid = (size_t)blockIdx.x * blockDim.x + threadIdx.x;
    size_t st  = (size_t)gridDim.x * blockDim.x;
    const size_t nh0 = (size_t)2 * 16 * 64 * 4096;
    const size_t nh1 = (size_t)2 * 16 * 6 * 4096;
    const size_t nc0 = (size_t)16 * 128 * 4096;
    const size_t nc1 = (size_t)16 * 12 * 4096;
    for (size_t i = tid; i < nh0; i += st) g_h0p[i] = 0u;
    for (size_t i = tid; i < nh1; i += st) g_h1p[i] = 0u;
    for (size_t i = tid; i < nc0; i += st) g_c0[i] = 0.f;
    for (size_t i = tid; i < nc1; i += st) g_c1[i] = 0.f;
}

__global__ void xprep_kernel(const float* __restrict__ hist) {
    int n = TSTEPS * 16 * 4096;
    for (int i = blockIdx.x * blockDim.x + threadIdx.x; i < n;
         i += gridDim.x * blockDim.x) {
        int px = i & 4095, b = (i >> 12) & 15, t = i >> 16;
        float v = hist[((size_t)b * TSTEPS + t) * 4096 + px];
        g_xp[((size_t)t * 16 + b) * 4096 + px] = pack_hf(v, 0.f);
    }
}

// Weights -> A-fragment order: [hb][chunk][ (tap*4+g)*128 + lane*4 + r ]
// reg r: m = lane/4 + (r&1)*8 ; pair = lane%4 + ((r>>1)&1)*4
__global__ void repack_w(const float* __restrict__ W, uint32_t* __restrict__ Wp,
                         int HID, int CIN, int NHB, int layer) {
    int total = NHB * NCHUNK * 4608;
    for (int idx = blockIdx.x * blockDim.x + threadIdx.x; idx < total;
         idx += gridDim.x * blockDim.x) {
        int wrd = idx % 4608, rest = idx / 4608;
        int c = rest % NCHUNK, hb = rest / NCHUNK;
        int r = wrd & 3, lane = (wrd >> 2) & 31, gt = wrd >> 7;
        int g = gt & 3, t = gt >> 2;
        int m  = (lane >> 2) + (r & 1) * 8;
        int pr = (lane & 3) + ((r >> 1) & 1) * 4;
        int p  = c * 8 + pr;
        int hid = hb * 16 + m;
        int k0 = -1, k1 = -1;
        if (layer == 0) {
            if (p < 64)       { k0 = 2 * p + 1; k1 = 2 * p + 2; }
            else if (p == 64) { k0 = 0; }
        } else {
            if (p < 64)      { k0 = 2 * p; k1 = 2 * p + 1; }
            else if (p < 70) { k0 = 128 + 2 * (p - 64); k1 = k0 + 1; }
        }
        float w0 = 0.f, w1 = 0.f;
        if (hid < HID) {
            if (k0 >= 0) w0 = W[((size_t)(g * HID + hid) * CIN + k0) * 9 + t];
            if (k1 >= 0) w1 = W[((size_t)(g * HID + hid) * CIN + k1) * 9 + t];
        }
        Wp[idx] = pack_hf(w0, w1);
    }
}

// -------------------- fused conv + LSTM step --------------------------------
// Grid (16 y-tiles, NHB, 16 batch), block 256 = 8 warps (wx 0..7).
// Warp: 16 hid x 4 gates x 32 px (8-px strip, 4 rows). 64 f32 accs/thread.
// Weights: per-tap LDG.128 fragments straight from global (L1-cached).
template <int NPA, int NPB, int HID>
__global__ __launch_bounds__(256, 2)
void conv_step(const uint32_t* __restrict__ actA,   // [b][NPA][4096]
               const uint32_t* __restrict__ actB,   // [b][NPB][4096]
               const uint32_t* __restrict__ Wg,     // [hb][9][4608] frag order
               const float*    __restrict__ bias,
               float*          __restrict__ cbuf,   // [b][HID][4096]
               uint32_t*       __restrict__ hout,   // [b][HID/2][4096]
               float*          __restrict__ hfout) {
    extern __shared__ uint32_t sm[];
    const int tid = threadIdx.x;
    const int lane = tid & 31, warp = tid >> 5;
    const int tg = lane & 3, gq = lane >> 2;
    const int wx = warp;                 // 0..7 (8-px strip)
    const int y0 = blockIdx.x * 4;
    const int hb = blockIdx.y;
    const int b  = blockIdx.z;
    const uint32_t* wgm = Wg + (size_t)hb * NCHUNK * 4608 + lane * 4;

    // zero halo columns (words 0..3 / 68..71) for all planes, both act buffers
    if (tid < 192) {
        int side = tid & 1, v = tid >> 1;          // v 0..95
        int r = v % 6, p = (v / 6) & 7, bfi = v / 48;
        uint32_t* dst = sm + bfi * SW_ACT + p * 440 + r * 72 + (side ? 68 : 0);
        *(uint4*)dst = make_uint4(0, 0, 0, 0);
    }

    float acc[4][4][4];
#pragma unroll
    for (int g = 0; g < 4; g++)
#pragma unroll
        for (int n = 0; n < 4; n++)
#pragma unroll
            for (int r = 0; r < 4; r++) acc[g][n][r] = 0.f;

    auto ldchunk = [&](int c, int bfi) {
#pragma unroll
        for (int k = 0; k < 3; k++) {
            int u = tid + k * 256;               // 768 uint4: act data
            int p = u & 7, rest = u >> 3;        // rest 0..95
            int r = rest % 6, seg = rest / 6;    // seg: 16 x 4px
            int pair = c * 8 + p;
            int y = y0 + r - 1;
            uint32_t* dst = sm + bfi * SW_ACT + p * 440 + r * 72 + 4 + seg * 4;
            const uint32_t* src = nullptr;
            if ((unsigned)y < 64u) {
                if (pair < NPA)
                    src = actA + ((size_t)b * NPA + pair) * 4096 + y * 64 + seg * 4;
                else if (pair < NPA + NPB)
                    src = actB + ((size_t)b * NPB + (pair - NPA)) * 4096 +
                          y * 64 + seg * 4;
            }
            if (src) cpa16(smaddr(dst), src);
            else     *(uint4*)dst = make_uint4(0, 0, 0, 0);
        }
        asm volatile("cp.async.commit_group;");
    };

    ldchunk(0, 0);

    for (int c = 0; c < NCHUNK; c++) {
        const int bfi = c & 1;
        if (c + 1 < NCHUNK) {
            ldchunk(c + 1, bfi ^ 1);
            asm volatile("cp.async.wait_group 1;");
        } else {
            asm volatile("cp.async.wait_group 0;");
        }
        __syncthreads();

        const uint32_t* aB = sm + bfi * SW_ACT;
        const uint32_t* wc = wgm + (size_t)c * 4608;

#pragma unroll
        for (int ky = 0; ky < 3; ky++) {
#pragma unroll
            for (int kx = 0; kx < 3; kx++) {
                const int t = ky * 3 + kx;
                const int cb = 4 + wx * 8 + gq + kx - 1;
                // stage weight fragments for this tap (4 x LDG.128, L1-hot)
                uint4 ah[4];
#pragma unroll
                for (int g = 0; g < 4; g++)
                    ah[g] = __ldg((const uint4*)(wc + (t * 4 + g) * 128));
                uint32_t bh[4][2];
#pragma unroll
                for (int nt = 0; nt < 4; nt++) {
                    int o0 = tg * 440 + (ky + nt) * 72 + cb;
                    bh[nt][0] = aB[o0]; bh[nt][1] = aB[o0 + 4 * 440];
                }
#pragma unroll
                for (int g = 0; g < 4; g++) {
#pragma unroll
                    for (int nt = 0; nt < 4; nt++)
                        mma_f16(acc[g][nt], (const uint32_t*)&ah[g],
                                bh[nt][0], bh[nt][1]);
                }
            }
        }
        __syncthreads();
    }

    // ---- LSTM epilogue -----------------------------------------------------
    const int xpx = wx * 8 + tg * 2;
#pragma unroll
    for (int part = 0; part < 2; part++) {
        const int hid = hb * 16 + gq + part * 8;
        const bool hv = (hid < HID);
        float bi = 0.f, bfv = 0.f, bo = 0.f, bg = 0.f;
        if (hv) {
            bi = bias[hid]; bfv = bias[HID + hid];
            bo = bias[2 * HID + hid]; bg = bias[3 * HID + hid];
        }
#pragma unroll
        for (int nt = 0; nt < 4; nt++) {
            const int y = y0 + nt;
            const size_t coff =
                ((size_t)(b * HID + (hv ? hid : 0))) * 4096 + (size_t)y * 64 + xpx;
            float2 c2 = hv ? *(const float2*)(cbuf + coff) : make_float2(0.f, 0.f);
            float cold[2] = {c2.x, c2.y}, hn[2];
#pragma unroll
            for (int q = 0; q < 2; q++) {
                float I = sigf(acc[0][nt][part * 2 + q] + bi);
                float F = sigf(acc[1][nt][part * 2 + q] + bfv);
                float O = sigf(acc[2][nt][part * 2 + q] + bo);
                float G = tanh_fast(acc[3][nt][part * 2 + q] + bg);
                float cn = F * cold[q] + I * G;
                cold[q] = cn;
                hn[q] = O * tanh_fast(cn);
            }
            if (hv) {
                *(float2*)(cbuf + coff) = make_float2(cold[0], cold[1]);
                if (hfout)
                    *(float2*)(hfout + coff) = make_float2(hn[0], hn[1]);
            }
            // pack channel pairs: partner hid^1 lives at lane^4
            float pn0 = __shfl_xor_sync(0xffffffffu, hn[0], 4);
            float pn1 = __shfl_xor_sync(0xffffffffu, hn[1], 4);
            if (((gq & 1) == 0) && hv) {
                const int qp = hid >> 1;
                const size_t ob =
                    ((size_t)b * (HID / 2) + qp) * 4096 + (size_t)y * 64 + xpx;
                *(uint2*)(hout + ob) =
                    make_uint2(pack_hf(hn[0], pn0), pack_hf(hn[1], pn1));
            }
        }
    }
}

// -------------------- host driver -------------------------------------------
extern "C" void kernel_launch(void* const* d_in, const int* in_sizes, int n_in,
                              void* d_out, int out_size) {
    (void)in_sizes; (void)n_in; (void)out_size;
    const float* history = (const float*)d_in[0];
    const float* W0 = (const float*)d_in[2];
    const float* b0 = (const float*)d_in[3];
    const float* W1 = (const float*)d_in[4];
    const float* b1 = (const float*)d_in[5];

    uint32_t *h0p, *h1p, *xp, *wp0, *wp1;
    float *c0, *c1, *h1f;
    cudaGetSymbolAddress((void**)&h0p, g_h0p);
    cudaGetSymbolAddress((void**)&h1p, g_h1p);
    cudaGetSymbolAddress((void**)&xp,  g_xp);
    cudaGetSymbolAddress((void**)&wp0, g_wp0);
    cudaGetSymbolAddress((void**)&wp1, g_wp1);
    cudaGetSymbolAddress((void**)&c0,  g_c0);
    cudaGetSymbolAddress((void**)&c1,  g_c1);
    cudaGetSymbolAddress((void**)&h1f, g_h1f);

    zero_init_kernel<<<1024, 256>>>();
    xprep_kernel<<<768, 256>>>(history);
    repack_w<<<324, 256>>>(W0, wp0, 128, 129, 8, 0);
    repack_w<<<41, 256>>>(W1, wp1, 12, 140, 1, 1);

    const size_t H0SZ = (size_t)16 * 64 * 4096;
    const size_t H1SZ = (size_t)16 * 6 * 4096;

    int pa = 0;
    for (int t = 0; t < TSTEPS; t++) {
        const uint32_t* h0r = h0p + (size_t)pa * H0SZ;
        uint32_t*       h0w = h0p + (size_t)(1 - pa) * H0SZ;
        const uint32_t* h1r = h1p + (size_t)pa * H1SZ;
        uint32_t*       h1w = h1p + (size_t)(1 - pa) * H1SZ;

        conv_step<64, 1, 128><<<dim3(16, 8, 16), 256, SMEM_BYTES>>>(
            h0r, xp + (size_t)t * 16 * 4096, wp0, b0, c0, h0w, nullptr);

        conv_step<64, 6, 12><<<dim3(16, 1, 16), 256, SMEM_BYTES>>>(
            h0w, h1r, wp1, b1, c1, h1w, h1f);

        pa ^= 1;
    }

    cudaMemcpyAsync(d_out, h1f, (size_t)16 * 12 * 4096 * sizeof(float),
                    cudaMemcpyDeviceToDevice);
}